// round 2
// baseline (speedup 1.0000x reference)
#include <cuda_runtime.h>
#include <math.h>

#define H_DIM  2048
#define N_EXP  64
#define TOPK   8
#define KC     32      // K-chunk per smem stage
#define TILE_M 128     // tokens per block
#define NTHR   256

// smem: fill phase uses xs[128][32] (16KB) + ws[64][32] (8KB) = 24KB
//       epilogue reuses same buffer as scores[128][65] = 33280B
#define SMEM_FLOATS (TILE_M * (N_EXP + 1))   // 8320 floats (> 6144 fill floats)

__global__ __launch_bounds__(NTHR) void moe_gate_kernel(
    const float* __restrict__ x,      // (T, H)
    const float* __restrict__ w,      // (E, H)
    float* __restrict__ out,
    int T, int two_outputs)
{
    __shared__ __align__(16) float smem[SMEM_FLOATS];
    float* xs  = smem;                     // [TILE_M][KC], swizzled
    float* wsm = smem + TILE_M * KC;       // [N_EXP][KC], swizzled
    float* sc  = smem;                     // [TILE_M][N_EXP+1] (epilogue reuse)

    const int tid = threadIdx.x;
    const int r   = tid >> 3;    // 0..31
    const int c   = tid & 7;     // 0..7
    const int tm  = r * 4;       // 4 token rows per thread
    const int tn  = c * 8;       // 8 expert cols per thread
    const int blk = blockIdx.x;

    const float* xblk = x + (size_t)blk * TILE_M * H_DIM;

    // swizzle constants (constant per thread: tm..tm+3 share tm>>3; tn..tn+7 share tn>>3)
    const int swa = ((tm >> 3) & 7) << 2;
    const int swb = c << 2;

    // fill-phase coordinates
    const int fm = tid >> 3;          // 0..31
    const int fk = (tid & 7) * 4;     // float4 column
    const int xsw = fk ^ (((fm >> 3) & 7) << 2);  // same swizzle for all fill rows (fm, fm+32.. share fm>>3 & 3 bits? no)
    // note: rows fm, fm+32, fm+64, fm+96 have different (m>>3)&7 — compute per row below.

    float acc[4][8];
    #pragma unroll
    for (int i = 0; i < 4; i++)
        #pragma unroll
        for (int j = 0; j < 8; j++) acc[i][j] = 0.0f;

    // ---- prologue: load first chunk into registers ----
    float4 px[4], pw[2];
    #pragma unroll
    for (int i = 0; i < 4; i++)
        px[i] = *(const float4*)(xblk + (size_t)(fm + i * 32) * H_DIM + fk);
    #pragma unroll
    for (int i = 0; i < 2; i++)
        pw[i] = *(const float4*)(w + (size_t)(fm + i * 32) * H_DIM + fk);

    for (int k0 = 0; k0 < H_DIM; k0 += KC) {
        // ---- store prefetched chunk to smem ----
        #pragma unroll
        for (int i = 0; i < 4; i++) {
            int m = fm + i * 32;
            int ksw = fk ^ (((m >> 3) & 7) << 2);
            *(float4*)&xs[m * KC + ksw] = px[i];
        }
        #pragma unroll
        for (int i = 0; i < 2; i++) {
            int e = fm + i * 32;
            int ksw = fk ^ (((e >> 3) & 7) << 2);
            *(float4*)&wsm[e * KC + ksw] = pw[i];
        }
        __syncthreads();

        // ---- prefetch next chunk (overlaps with compute below) ----
        int kn = k0 + KC;
        if (kn < H_DIM) {
            #pragma unroll
            for (int i = 0; i < 4; i++)
                px[i] = *(const float4*)(xblk + (size_t)(fm + i * 32) * H_DIM + kn + fk);
            #pragma unroll
            for (int i = 0; i < 2; i++)
                pw[i] = *(const float4*)(w + (size_t)(fm + i * 32) * H_DIM + kn + fk);
        }

        // ---- compute: per k4-step, 4+8 LDS.128 + 128 FFMA ----
        #pragma unroll
        for (int kk = 0; kk < KC; kk += 4) {
            float4 a4[4], b4[8];
            #pragma unroll
            for (int i = 0; i < 4; i++)
                a4[i] = *(const float4*)&xs[(tm + i) * KC + (kk ^ swa)];
            #pragma unroll
            for (int j = 0; j < 8; j++)
                b4[j] = *(const float4*)&wsm[(tn + j) * KC + (kk ^ swb)];
            #pragma unroll
            for (int i = 0; i < 4; i++)
                #pragma unroll
                for (int j = 0; j < 8; j++) {
                    acc[i][j] += a4[i].x * b4[j].x;
                    acc[i][j] += a4[i].y * b4[j].y;
                    acc[i][j] += a4[i].z * b4[j].z;
                    acc[i][j] += a4[i].w * b4[j].w;
                }
        }
        __syncthreads();
    }

    // ---- epilogue: dump scores to smem, then 1 thread per token ----
    #pragma unroll
    for (int i = 0; i < 4; i++)
        #pragma unroll
        for (int j = 0; j < 8; j++)
            sc[(tm + i) * (N_EXP + 1) + tn + j] = acc[i][j];
    __syncthreads();

    if (tid < TILE_M) {
        const float* row = &sc[tid * (N_EXP + 1)];

        float mx = row[0];
        #pragma unroll
        for (int e = 1; e < N_EXP; e++) mx = fmaxf(mx, row[e]);

        // top-8 selection on raw scores (softmax is monotonic; global
        // denominator cancels under top-k renormalization).
        // Strictly-greater comparison => earliest index wins ties (matches lax.top_k).
        unsigned long long used = 0ULL;
        int   idxs[TOPK];
        float vals[TOPK];
        #pragma unroll
        for (int k = 0; k < TOPK; k++) {
            float best = -INFINITY;
            int   bi   = 0;
            for (int e = 0; e < N_EXP; e++) {
                if (!((used >> e) & 1ULL)) {
                    float v = row[e];
                    if (v > best) { best = v; bi = e; }
                }
            }
            used |= 1ULL << bi;
            idxs[k] = bi;
            vals[k] = best;
        }

        float ew[TOPK];
        float sumw = 0.0f;
        #pragma unroll
        for (int k = 0; k < TOPK; k++) {
            ew[k] = expf(vals[k] - mx);
            sumw += ew[k];
        }
        float inv = 1.0f / sumw;

        size_t t = (size_t)blk * TILE_M + tid;
        if (two_outputs) {
            // layout guess: flattened topk_idx (cast to float) then flattened topk_weight
            #pragma unroll
            for (int k = 0; k < TOPK; k++) {
                out[t * TOPK + k] = (float)idxs[k];
                out[(size_t)T * TOPK + t * TOPK + k] = ew[k] * inv;
            }
        } else {
            #pragma unroll
            for (int k = 0; k < TOPK; k++)
                out[t * TOPK + k] = ew[k] * inv;
        }
    }
}

extern "C" void kernel_launch(void* const* d_in, const int* in_sizes, int n_in,
                              void* d_out, int out_size) {
    const float* x = (const float*)d_in[0];   // hidden_states (B,S,H) flattened
    const float* w = (const float*)d_in[1];   // weight (E,H)
    int T = in_sizes[0] / H_DIM;              // 16384
    int two = (out_size >= 2 * T * TOPK) ? 1 : 0;
    int grid = T / TILE_M;                    // 128
    moe_gate_kernel<<<grid, NTHR>>>(x, w, (float*)d_out, T, two);
}